// round 9
// baseline (speedup 1.0000x reference)
#include <cuda_runtime.h>
#include <cuda_fp16.h>
#include <cstdint>

#define BB 32
#define NN 512
#define DD 256
#define NEG_INF -9e15f

// ---------------------------------------------------------------------------
// Device scratch (no allocation allowed)
// ---------------------------------------------------------------------------
__device__ __half g_ehi[(size_t)BB * 4 * NN * NN];     // raw scores hi (fp16)
__device__ __half g_elo[(size_t)BB * 4 * NN * NN];     // raw scores lo (fp16)
__device__ __half g_a[(size_t)BB * NN * NN];           // alpha (fp16, unsplit)
__device__ __half g_whi[(size_t)BB * 4 * NN * DD];     // (h*a_k) hi
__device__ __half g_wlo[(size_t)BB * 4 * NN * DD];     // (h*a_k) lo
__device__ __half g_bhi[(size_t)BB * NN * DD];         // h hi
__device__ __half g_blo[(size_t)BB * NN * DD];         // h lo

// ---------------------------------------------------------------------------
// mma.sync / cp.async helpers (portable sm_80+ path; tcgen05 blocked by the
// harness's compute_103 PTX stage)
// ---------------------------------------------------------------------------
__device__ __forceinline__ uint32_t smem_to_u32(const void* p) {
    uint32_t a;
    asm("{ .reg .u64 t; cvta.to.shared.u64 t, %1; cvt.u32.u64 %0, t; }"
        : "=r"(a) : "l"(p));
    return a;
}
__device__ __forceinline__ void ldm_x4(uint32_t* r, uint32_t addr) {
    asm volatile("ldmatrix.sync.aligned.m8n8.x4.shared.b16 {%0,%1,%2,%3}, [%4];"
        : "=r"(r[0]), "=r"(r[1]), "=r"(r[2]), "=r"(r[3]) : "r"(addr));
}
__device__ __forceinline__ void ldm_x4_trans(uint32_t* r, uint32_t addr) {
    asm volatile("ldmatrix.sync.aligned.m8n8.x4.trans.shared.b16 {%0,%1,%2,%3}, [%4];"
        : "=r"(r[0]), "=r"(r[1]), "=r"(r[2]), "=r"(r[3]) : "r"(addr));
}
__device__ __forceinline__ void mma16816(float* c, const uint32_t* a, const uint32_t* b) {
    asm volatile(
        "mma.sync.aligned.m16n8k16.row.col.f32.f16.f16.f32 "
        "{%0,%1,%2,%3}, {%4,%5,%6,%7}, {%8,%9}, {%0,%1,%2,%3};"
        : "+f"(c[0]), "+f"(c[1]), "+f"(c[2]), "+f"(c[3])
        : "r"(a[0]), "r"(a[1]), "r"(a[2]), "r"(a[3]), "r"(b[0]), "r"(b[1]));
}
__device__ __forceinline__ void cp16(uint32_t dst, const void* src) {
    asm volatile("cp.async.cg.shared.global [%0], [%1], 16;" :: "r"(dst), "l"(src));
}
#define CP_COMMIT() asm volatile("cp.async.commit_group;" ::: "memory")
#define CP_WAIT0()  asm volatile("cp.async.wait_group 0;" ::: "memory")

// ---------------------------------------------------------------------------
// K0: split h and w_k = h*a_k into fp16 hi/lo planes
// ---------------------------------------------------------------------------
__device__ __forceinline__ void f16pair_store(
    __half* hi, __half* lo, float4 v)
{
    float f[4] = {v.x, v.y, v.z, v.w};
    __half hb[4], lb[4];
#pragma unroll
    for (int j = 0; j < 4; j++) {
        hb[j] = __float2half_rn(f[j]);
        lb[j] = __float2half_rn(f[j] - __half2float(hb[j]));
    }
    ((__half2*)hi)[0] = __half2(hb[0], hb[1]);
    ((__half2*)hi)[1] = __half2(hb[2], hb[3]);
    ((__half2*)lo)[0] = __half2(lb[0], lb[1]);
    ((__half2*)lo)[1] = __half2(lb[2], lb[3]);
}

__global__ __launch_bounds__(256) void k_split(
    const float* __restrict__ h,
    const float* __restrict__ a0, const float* __restrict__ a1,
    const float* __restrict__ a2, const float* __restrict__ a3)
{
    const int idx = blockIdx.x * 256 + threadIdx.x;
    const int row = idx >> 6;
    const int c4  = idx & 63;
    const int d   = c4 * 4;
    const float4 hv = ((const float4*)h)[idx];

    {
        size_t off = (size_t)row * DD + d;
        f16pair_store(g_bhi + off, g_blo + off, hv);
    }
    const int b = row >> 9, i = row & 511;
    const float* aks[4] = {a0, a1, a2, a3};
#pragma unroll
    for (int k = 0; k < 4; k++) {
        const float4 av = ((const float4*)aks[k])[c4];
        float4 wv = make_float4(hv.x * av.x, hv.y * av.y, hv.z * av.z, hv.w * av.w);
        size_t off = (((size_t)b * 4 + k) * NN + i) * DD + d;
        f16pair_store(g_whi + off, g_wlo + off, wv);
    }
}

// ---------------------------------------------------------------------------
// K1: tensor scores (fp16 hi/lo 3-pass), 2-stage cp.async, one barrier/chunk.
// CTA = (b, head, 128i x 128j). 8 warps 4(i) x 2(j), warp tile 32 x 64.
// Epilogue stores e as fp16 hi/lo pairs (halves score-plane traffic).
// ---------------------------------------------------------------------------
#define SAS 40                       // 32 fp16 + 8 pad
#define S_PLANE (128 * SAS)
#define S_STAGE (4 * S_PLANE)        // whi, wlo, bhi, blo
#define S_SMEM_BYTES (2 * S_STAGE * 2)

__global__ void __launch_bounds__(256, 2) k_scores_tc()
{
    extern __shared__ __half sm[];

    const int t    = threadIdx.x;
    const int w    = t >> 5;
    const int lane = t & 31;
    const int wi   = w & 3;
    const int wj   = w >> 2;
    const int b    = blockIdx.z;
    const int k    = blockIdx.y >> 2;
    const int i0   = (blockIdx.y & 3) * 128;
    const int j0   = blockIdx.x * 128;

    const uint32_t smu = smem_to_u32(sm);

    const size_t aoff = (((size_t)b * 4 + k) * NN + i0) * DD;
    const size_t boff = ((size_t)b * NN + j0) * DD;
    const __half* gA0 = g_whi + aoff;
    const __half* gA1 = g_wlo + aoff;
    const __half* gB0 = g_bhi + boff;
    const __half* gB1 = g_blo + boff;

    float acc[2][8][4];
#pragma unroll
    for (int m = 0; m < 2; m++)
#pragma unroll
        for (int n = 0; n < 8; n++)
#pragma unroll
            for (int q = 0; q < 4; q++) acc[m][n][q] = 0.f;

    const uint32_t a_row  = wi * 32 + (lane & 15);
    const uint32_t a_colb = (lane >> 4) * 8;
    const uint32_t b_row  = wj * 64 + (lane & 7) + (lane >> 4) * 8;
    const uint32_t b_colb = ((lane >> 3) & 1) * 8;

    auto load_stage = [&](int st, int d0) {
        const uint32_t s0 = smu + (uint32_t)(st * S_STAGE) * 2;
#pragma unroll
        for (int q = t; q < 512; q += 256) {
            const int r = q >> 2;
            const int c = (q & 3) * 8;
            const uint32_t so = (uint32_t)(r * SAS + c) * 2;
            const size_t go = (size_t)r * DD + d0 + c;
            cp16(s0 + 0 * S_PLANE * 2 + so, gA0 + go);
            cp16(s0 + 1 * S_PLANE * 2 + so, gA1 + go);
            cp16(s0 + 2 * S_PLANE * 2 + so, gB0 + go);
            cp16(s0 + 3 * S_PLANE * 2 + so, gB1 + go);
        }
    };

    load_stage(0, 0);
    CP_COMMIT();

    const int NCH = DD / 32;   // 8 chunks
    for (int c = 0; c < NCH; c++) {
        CP_WAIT0();
        __syncthreads();
        if (c + 1 < NCH) {
            load_stage((c + 1) & 1, (c + 1) * 32);
            CP_COMMIT();
        }

        const uint32_t s0   = smu + (uint32_t)((c & 1) * S_STAGE) * 2;
        const uint32_t sWhi = s0;
        const uint32_t sWlo = s0 + 1 * S_PLANE * 2;
        const uint32_t sBhi = s0 + 2 * S_PLANE * 2;
        const uint32_t sBlo = s0 + 3 * S_PLANE * 2;

#pragma unroll
        for (int ks = 0; ks < 2; ks++) {
            uint32_t ahi[2][4], alo[2][4];
#pragma unroll
            for (int mt = 0; mt < 2; mt++) {
                const uint32_t off = ((a_row + mt * 16) * SAS + ks * 16 + a_colb) * 2;
                ldm_x4(ahi[mt], sWhi + off);
                ldm_x4(alo[mt], sWlo + off);
            }
#pragma unroll
            for (int ntp = 0; ntp < 4; ntp++) {
                uint32_t bh[4], bl[4];
                const uint32_t off = ((b_row + ntp * 16) * SAS + ks * 16 + b_colb) * 2;
                ldm_x4(bh, sBhi + off);
                ldm_x4(bl, sBlo + off);
#pragma unroll
                for (int mt = 0; mt < 2; mt++) {
                    mma16816(acc[mt][ntp*2],   ahi[mt], bh);
                    mma16816(acc[mt][ntp*2+1], ahi[mt], bh + 2);
                    mma16816(acc[mt][ntp*2],   ahi[mt], bl);
                    mma16816(acc[mt][ntp*2+1], ahi[mt], bl + 2);
                    mma16816(acc[mt][ntp*2],   alo[mt], bh);
                    mma16816(acc[mt][ntp*2+1], alo[mt], bh + 2);
                }
            }
        }
    }

    // epilogue -> fp16 hi/lo e planes
    const int g  = lane >> 2;
    const int tt = lane & 3;
    const size_t pbase = (((size_t)b * 4 + k) * NN + i0) * NN + j0;
    __half* phi = g_ehi + pbase;
    __half* plo = g_elo + pbase;
#pragma unroll
    for (int mt = 0; mt < 2; mt++) {
        const int r0 = wi * 32 + mt * 16 + g;
#pragma unroll
        for (int nt = 0; nt < 8; nt++) {
            const int c0 = wj * 64 + nt * 8 + tt * 2;
#pragma unroll
            for (int hrow = 0; hrow < 2; hrow++) {
                const size_t off = (size_t)(r0 + hrow * 8) * NN + c0;
                const float v0 = acc[mt][nt][hrow * 2 + 0];
                const float v1 = acc[mt][nt][hrow * 2 + 1];
                const __half h0 = __float2half_rn(v0);
                const __half h1 = __float2half_rn(v1);
                *(__half2*)&phi[off] = __half2(h0, h1);
                *(__half2*)&plo[off] = __half2(
                    __float2half_rn(v0 - __half2float(h0)),
                    __float2half_rn(v1 - __half2float(h1)));
            }
        }
    }
}

// ---------------------------------------------------------------------------
// K2: fused adj-select + leaky-relu + softmax -> fp16 alpha (single plane)
// ---------------------------------------------------------------------------
__global__ __launch_bounds__(256) void k_sel_softmax(const int* __restrict__ adj)
{
    const int w    = threadIdx.x >> 5;
    const int lane = threadIdx.x & 31;
    const size_t row = (size_t)blockIdx.x * 8 + w;
    const int b = (int)(row >> 9);
    const int i = (int)(row & 511);

    const size_t pstride = (size_t)NN * NN;
    const size_t rbase = (((size_t)b * 4 + 0) * NN + i) * NN;
    const int* ar = adj + row * NN;

    float v[16];
#pragma unroll
    for (int q = 0; q < 4; q++) {
        const int idx = q * 32 + lane;   // 4-element group
        float e4[4][4];                  // [head][elem]
#pragma unroll
        for (int hk = 0; hk < 4; hk++) {
            const uint2 hi2 = ((const uint2*)(g_ehi + rbase + hk * pstride))[idx];
            const uint2 lo2 = ((const uint2*)(g_elo + rbase + hk * pstride))[idx];
            const __half2 h0 = *(const __half2*)&hi2.x;
            const __half2 h1 = *(const __half2*)&hi2.y;
            const __half2 l0 = *(const __half2*)&lo2.x;
            const __half2 l1 = *(const __half2*)&lo2.y;
            const float2 fh0 = __half22float2(h0), fh1 = __half22float2(h1);
            const float2 fl0 = __half22float2(l0), fl1 = __half22float2(l1);
            e4[hk][0] = fh0.x + fl0.x; e4[hk][1] = fh0.y + fl0.y;
            e4[hk][2] = fh1.x + fl1.x; e4[hk][3] = fh1.y + fl1.y;
        }
        const int4 c = ((const int4*)ar)[idx];
        const int cc[4] = {c.x, c.y, c.z, c.w};
#pragma unroll
        for (int j = 0; j < 4; j++) {
            const int c1 = cc[j];
            if (c1 >= 1 && c1 <= 4) {
                const float e = e4[c1 - 1][j];
                v[q * 4 + j] = (e > 0.f) ? e : 0.2f * e;
            } else {
                v[q * 4 + j] = NEG_INF;
            }
        }
    }

    float m = v[0];
#pragma unroll
    for (int q = 1; q < 16; q++) m = fmaxf(m, v[q]);
#pragma unroll
    for (int o = 16; o > 0; o >>= 1) m = fmaxf(m, __shfl_xor_sync(0xffffffffu, m, o));

    float sum = 0.f;
#pragma unroll
    for (int q = 0; q < 16; q++) { v[q] = __expf(v[q] - m); sum += v[q]; }
#pragma unroll
    for (int o = 16; o > 0; o >>= 1) sum += __shfl_xor_sync(0xffffffffu, sum, o);

    const float inv = 1.f / sum;
    __half* ap = g_a + row * NN;
#pragma unroll
    for (int q = 0; q < 4; q++) {
        const int idx = q * 32 + lane;
        __half hb[4];
#pragma unroll
        for (int j = 0; j < 4; j++)
            hb[j] = __float2half_rn(v[q * 4 + j] * inv);
        ((__half2*)(ap + idx * 4))[0] = __half2(hb[0], hb[1]);
        ((__half2*)(ap + idx * 4))[1] = __half2(hb[2], hb[3]);
    }
}

// ---------------------------------------------------------------------------
// K3: out = alpha @ h. Alpha unsplit fp16 (2 passes: a*bhi + a*blo).
// 2-stage cp.async, one barrier per chunk. (exact R7 geometry)
// ---------------------------------------------------------------------------
#define VBS 136                        // 128 fp16 + 8 pad
#define V_APLANE (128 * SAS)
#define V_BPLANE (32 * VBS)
#define V_STAGE  (V_APLANE + 2 * V_BPLANE)
#define V_SMEM_BYTES (2 * V_STAGE * 2)

__global__ void __launch_bounds__(256, 2) k_av_tc(float* __restrict__ out)
{
    extern __shared__ __half sm[];

    const int t    = threadIdx.x;
    const int w    = t >> 5;
    const int lane = t & 31;
    const int wi   = w & 3;
    const int wj   = w >> 2;
    const int b    = blockIdx.z;
    const int i0   = blockIdx.y * 128;
    const int d0   = blockIdx.x * 128;

    const uint32_t smu = smem_to_u32(sm);

    const size_t aoff = ((size_t)b * NN + i0) * NN;
    const size_t boff = (size_t)b * NN * DD;
    const __half* gA0 = g_a + aoff;
    const __half* gB0 = g_bhi + boff;
    const __half* gB1 = g_blo + boff;

    float acc[2][8][4];
#pragma unroll
    for (int m = 0; m < 2; m++)
#pragma unroll
        for (int n = 0; n < 8; n++)
#pragma unroll
            for (int q = 0; q < 4; q++) acc[m][n][q] = 0.f;

    const uint32_t a_row  = wi * 32 + (lane & 15);
    const uint32_t a_colb = (lane >> 4) * 8;
    const uint32_t bt_row = lane & 15;
    const uint32_t bt_col = wj * 64 + (lane >> 4) * 8;

    auto load_stage = [&](int st, int j0c) {
        const uint32_t s0 = smu + (uint32_t)(st * V_STAGE) * 2;
#pragma unroll
        for (int q = t; q < 512; q += 256) {
            const int r = q >> 2;
            const int c = (q & 3) * 8;
            const uint32_t so = (uint32_t)(r * SAS + c) * 2;
            cp16(s0 + so, gA0 + (size_t)r * NN + j0c + c);
        }
#pragma unroll
        for (int q = t; q < 512; q += 256) {
            const int r = q >> 4;
            const int c = (q & 15) * 8;
            const uint32_t so = (uint32_t)(r * VBS + c) * 2;
            const size_t go = (size_t)(j0c + r) * DD + d0 + c;
            cp16(s0 + V_APLANE * 2 + so, gB0 + go);
            cp16(s0 + V_APLANE * 2 + V_BPLANE * 2 + so, gB1 + go);
        }
    };

    load_stage(0, 0);
    CP_COMMIT();

    const int NCH = NN / 32;   // 16 chunks
    for (int c = 0; c < NCH; c++) {
        CP_WAIT0();
        __syncthreads();
        if (c + 1 < NCH) {
            load_stage((c + 1) & 1, (c + 1) * 32);
            CP_COMMIT();
        }

        const uint32_t s0   = smu + (uint32_t)((c & 1) * V_STAGE) * 2;
        const uint32_t sA   = s0;
        const uint32_t sBhi = s0 + V_APLANE * 2;
        const uint32_t sBlo = sBhi + V_BPLANE * 2;

#pragma unroll
        for (int ks = 0; ks < 2; ks++) {
            uint32_t afr[2][4];
#pragma unroll
            for (int mt = 0; mt < 2; mt++) {
                const uint32_t off = ((a_row + mt * 16) * SAS + ks * 16 + a_colb) * 2;
                ldm_x4(afr[mt], sA + off);
            }
#pragma unroll
            for (int ntp = 0; ntp < 4; ntp++) {
                uint32_t bh[4], bl[4];
                const uint32_t off = ((ks * 16 + bt_row) * VBS + bt_col + ntp * 16) * 2;
                ldm_x4_trans(bh, sBhi + off);
                ldm_x4_trans(bl, sBlo + off);
#pragma unroll
                for (int mt = 0; mt < 2; mt++) {
                    mma16816(acc[mt][ntp*2],   afr[mt], bh);
                    mma16816(acc[mt][ntp*2+1], afr[mt], bh + 2);
                }
#pragma unroll
                for (int mt = 0; mt < 2; mt++) {
                    mma16816(acc[mt][ntp*2],   afr[mt], bl);
                    mma16816(acc[mt][ntp*2+1], afr[mt], bl + 2);
                }
            }
        }
    }

    const int g  = lane >> 2;
    const int tt = lane & 3;
    float* obase = out + ((size_t)b * NN + i0) * DD + d0;
#pragma unroll
    for (int mt = 0; mt < 2; mt++) {
        const int r0 = wi * 32 + mt * 16 + g;
#pragma unroll
        for (int nt = 0; nt < 8; nt++) {
            const int c0 = wj * 64 + nt * 8 + tt * 2;
            *(float2*)&obase[(size_t)r0 * DD + c0]       = make_float2(acc[mt][nt][0], acc[mt][nt][1]);
            *(float2*)&obase[(size_t)(r0 + 8) * DD + c0] = make_float2(acc[mt][nt][2], acc[mt][nt][3]);
        }
    }
}

// ---------------------------------------------------------------------------
extern "C" void kernel_launch(void* const* d_in, const int* in_sizes, int n_in,
                              void* d_out, int out_size)
{
    const float* hidden = (const float*)d_in[0];
    const int*   adj    = (const int*)d_in[1];
    const float* a0     = (const float*)d_in[2];
    const float* a1     = (const float*)d_in[3];
    const float* a2     = (const float*)d_in[4];
    const float* a3     = (const float*)d_in[5];
    float* out = (float*)d_out;

    cudaFuncSetAttribute(k_scores_tc,
        cudaFuncAttributeMaxDynamicSharedMemorySize, S_SMEM_BYTES);
    cudaFuncSetAttribute(k_av_tc,
        cudaFuncAttributeMaxDynamicSharedMemorySize, V_SMEM_BYTES);

    k_split<<<(BB * NN * DD / 4) / 256, 256>>>(hidden, a0, a1, a2, a3);

    dim3 g1(NN / 128, 16, BB);
    k_scores_tc<<<g1, 256, S_SMEM_BYTES>>>();

    k_sel_softmax<<<(BB * NN) / 8, 256>>>(adj);

    dim3 g3(DD / 128, NN / 128, BB);
    k_av_tc<<<g3, 256, V_SMEM_BYTES>>>(out);
}

// round 10
// speedup vs baseline: 1.0645x; 1.0645x over previous
#include <cuda_runtime.h>
#include <cuda_fp16.h>
#include <cstdint>

#define BB 32
#define NN 512
#define DD 256
#define NEG_INF -9e15f

// ---------------------------------------------------------------------------
// Device scratch (no allocation allowed)
// ---------------------------------------------------------------------------
__device__ float g_e[(size_t)BB * 4 * NN * NN];        // per-head raw scores
__device__ __half g_a[(size_t)BB * NN * NN];           // alpha (fp16, unsplit)
__device__ __half g_whi[(size_t)BB * 4 * NN * DD];     // (h*a_k) hi
__device__ __half g_wlo[(size_t)BB * 4 * NN * DD];     // (h*a_k) lo
__device__ __half g_bhi[(size_t)BB * NN * DD];         // h hi
__device__ __half g_blo[(size_t)BB * NN * DD];         // h lo

// ---------------------------------------------------------------------------
// mma.sync / cp.async helpers (portable sm_80+ path; tcgen05 blocked by the
// harness's compute_103 PTX stage)
// ---------------------------------------------------------------------------
__device__ __forceinline__ uint32_t smem_to_u32(const void* p) {
    uint32_t a;
    asm("{ .reg .u64 t; cvta.to.shared.u64 t, %1; cvt.u32.u64 %0, t; }"
        : "=r"(a) : "l"(p));
    return a;
}
__device__ __forceinline__ void ldm_x4(uint32_t* r, uint32_t addr) {
    asm volatile("ldmatrix.sync.aligned.m8n8.x4.shared.b16 {%0,%1,%2,%3}, [%4];"
        : "=r"(r[0]), "=r"(r[1]), "=r"(r[2]), "=r"(r[3]) : "r"(addr));
}
__device__ __forceinline__ void ldm_x4_trans(uint32_t* r, uint32_t addr) {
    asm volatile("ldmatrix.sync.aligned.m8n8.x4.trans.shared.b16 {%0,%1,%2,%3}, [%4];"
        : "=r"(r[0]), "=r"(r[1]), "=r"(r[2]), "=r"(r[3]) : "r"(addr));
}
__device__ __forceinline__ void mma16816(float* c, const uint32_t* a, const uint32_t* b) {
    asm volatile(
        "mma.sync.aligned.m16n8k16.row.col.f32.f16.f16.f32 "
        "{%0,%1,%2,%3}, {%4,%5,%6,%7}, {%8,%9}, {%0,%1,%2,%3};"
        : "+f"(c[0]), "+f"(c[1]), "+f"(c[2]), "+f"(c[3])
        : "r"(a[0]), "r"(a[1]), "r"(a[2]), "r"(a[3]), "r"(b[0]), "r"(b[1]));
}
__device__ __forceinline__ void cp16(uint32_t dst, const void* src) {
    asm volatile("cp.async.cg.shared.global [%0], [%1], 16;" :: "r"(dst), "l"(src));
}
#define CP_COMMIT() asm volatile("cp.async.commit_group;" ::: "memory")
#define CP_WAIT0()  asm volatile("cp.async.wait_group 0;" ::: "memory")

// ---------------------------------------------------------------------------
// K0: split h and w_k = h*a_k into fp16 hi/lo planes
// ---------------------------------------------------------------------------
__device__ __forceinline__ void f16pair_store(
    __half* hi, __half* lo, float4 v)
{
    float f[4] = {v.x, v.y, v.z, v.w};
    __half hb[4], lb[4];
#pragma unroll
    for (int j = 0; j < 4; j++) {
        hb[j] = __float2half_rn(f[j]);
        lb[j] = __float2half_rn(f[j] - __half2float(hb[j]));
    }
    ((__half2*)hi)[0] = __half2(hb[0], hb[1]);
    ((__half2*)hi)[1] = __half2(hb[2], hb[3]);
    ((__half2*)lo)[0] = __half2(lb[0], lb[1]);
    ((__half2*)lo)[1] = __half2(lb[2], lb[3]);
}

__global__ __launch_bounds__(256) void k_split(
    const float* __restrict__ h,
    const float* __restrict__ a0, const float* __restrict__ a1,
    const float* __restrict__ a2, const float* __restrict__ a3)
{
    const int idx = blockIdx.x * 256 + threadIdx.x;
    const int row = idx >> 6;
    const int c4  = idx & 63;
    const int d   = c4 * 4;
    const float4 hv = ((const float4*)h)[idx];

    {
        size_t off = (size_t)row * DD + d;
        f16pair_store(g_bhi + off, g_blo + off, hv);
    }
    const int b = row >> 9, i = row & 511;
    const float* aks[4] = {a0, a1, a2, a3};
#pragma unroll
    for (int k = 0; k < 4; k++) {
        const float4 av = ((const float4*)aks[k])[c4];
        float4 wv = make_float4(hv.x * av.x, hv.y * av.y, hv.z * av.z, hv.w * av.w);
        size_t off = (((size_t)b * 4 + k) * NN + i) * DD + d;
        f16pair_store(g_whi + off, g_wlo + off, wv);
    }
}

// ---------------------------------------------------------------------------
// K1: tensor scores (fp16 hi/lo 3-pass), 2-stage cp.async, one barrier/chunk.
// CTA = (b, head, 128i x 128j). 8 warps 4(i) x 2(j), warp tile 32 x 64.
// MMA issue order: pass-grouped across mt (acc reuse distance 4, same regs).
// ---------------------------------------------------------------------------
#define SAS 40                       // 32 fp16 + 8 pad
#define S_PLANE (128 * SAS)
#define S_STAGE (4 * S_PLANE)        // whi, wlo, bhi, blo
#define S_SMEM_BYTES (2 * S_STAGE * 2)

__global__ void __launch_bounds__(256, 2) k_scores_tc()
{
    extern __shared__ __half sm[];

    const int t    = threadIdx.x;
    const int w    = t >> 5;
    const int lane = t & 31;
    const int wi   = w & 3;
    const int wj   = w >> 2;
    const int b    = blockIdx.z;
    const int k    = blockIdx.y >> 2;
    const int i0   = (blockIdx.y & 3) * 128;
    const int j0   = blockIdx.x * 128;

    const uint32_t smu = smem_to_u32(sm);

    const size_t aoff = (((size_t)b * 4 + k) * NN + i0) * DD;
    const size_t boff = ((size_t)b * NN + j0) * DD;
    const __half* gA0 = g_whi + aoff;
    const __half* gA1 = g_wlo + aoff;
    const __half* gB0 = g_bhi + boff;
    const __half* gB1 = g_blo + boff;

    float acc[2][8][4];
#pragma unroll
    for (int m = 0; m < 2; m++)
#pragma unroll
        for (int n = 0; n < 8; n++)
#pragma unroll
            for (int q = 0; q < 4; q++) acc[m][n][q] = 0.f;

    const uint32_t a_row  = wi * 32 + (lane & 15);
    const uint32_t a_colb = (lane >> 4) * 8;
    const uint32_t b_row  = wj * 64 + (lane & 7) + (lane >> 4) * 8;
    const uint32_t b_colb = ((lane >> 3) & 1) * 8;

    auto load_stage = [&](int st, int d0) {
        const uint32_t s0 = smu + (uint32_t)(st * S_STAGE) * 2;
#pragma unroll
        for (int q = t; q < 512; q += 256) {
            const int r = q >> 2;
            const int c = (q & 3) * 8;
            const uint32_t so = (uint32_t)(r * SAS + c) * 2;
            const size_t go = (size_t)r * DD + d0 + c;
            cp16(s0 + 0 * S_PLANE * 2 + so, gA0 + go);
            cp16(s0 + 1 * S_PLANE * 2 + so, gA1 + go);
            cp16(s0 + 2 * S_PLANE * 2 + so, gB0 + go);
            cp16(s0 + 3 * S_PLANE * 2 + so, gB1 + go);
        }
    };

    load_stage(0, 0);
    CP_COMMIT();

    const int NCH = DD / 32;   // 8 chunks
    for (int c = 0; c < NCH; c++) {
        CP_WAIT0();
        __syncthreads();
        if (c + 1 < NCH) {
            load_stage((c + 1) & 1, (c + 1) * 32);
            CP_COMMIT();
        }

        const uint32_t s0   = smu + (uint32_t)((c & 1) * S_STAGE) * 2;
        const uint32_t sWhi = s0;
        const uint32_t sWlo = s0 + 1 * S_PLANE * 2;
        const uint32_t sBhi = s0 + 2 * S_PLANE * 2;
        const uint32_t sBlo = s0 + 3 * S_PLANE * 2;

#pragma unroll
        for (int ks = 0; ks < 2; ks++) {
            uint32_t ahi[2][4], alo[2][4];
#pragma unroll
            for (int mt = 0; mt < 2; mt++) {
                const uint32_t off = ((a_row + mt * 16) * SAS + ks * 16 + a_colb) * 2;
                ldm_x4(ahi[mt], sWhi + off);
                ldm_x4(alo[mt], sWlo + off);
            }
#pragma unroll
            for (int ntp = 0; ntp < 4; ntp++) {
                uint32_t bh[4], bl[4];
                const uint32_t off = ((b_row + ntp * 16) * SAS + ks * 16 + b_colb) * 2;
                ldm_x4(bh, sBhi + off);
                ldm_x4(bl, sBlo + off);
                // pass 1: ahi * bh  (4 independent, reuse distance 4)
                mma16816(acc[0][ntp*2],   ahi[0], bh);
                mma16816(acc[0][ntp*2+1], ahi[0], bh + 2);
                mma16816(acc[1][ntp*2],   ahi[1], bh);
                mma16816(acc[1][ntp*2+1], ahi[1], bh + 2);
                // pass 2: ahi * bl
                mma16816(acc[0][ntp*2],   ahi[0], bl);
                mma16816(acc[0][ntp*2+1], ahi[0], bl + 2);
                mma16816(acc[1][ntp*2],   ahi[1], bl);
                mma16816(acc[1][ntp*2+1], ahi[1], bl + 2);
                // pass 3: alo * bh
                mma16816(acc[0][ntp*2],   alo[0], bh);
                mma16816(acc[0][ntp*2+1], alo[0], bh + 2);
                mma16816(acc[1][ntp*2],   alo[1], bh);
                mma16816(acc[1][ntp*2+1], alo[1], bh + 2);
            }
        }
    }

    // epilogue -> g_e plane
    const int g  = lane >> 2;
    const int tt = lane & 3;
    float* plane = g_e + (((size_t)b * 4 + k) * NN + i0) * NN + j0;
#pragma unroll
    for (int mt = 0; mt < 2; mt++) {
        const int r0 = wi * 32 + mt * 16 + g;
#pragma unroll
        for (int nt = 0; nt < 8; nt++) {
            const int c0 = wj * 64 + nt * 8 + tt * 2;
            *(float2*)&plane[(size_t)r0 * NN + c0]       = make_float2(acc[mt][nt][0], acc[mt][nt][1]);
            *(float2*)&plane[(size_t)(r0 + 8) * NN + c0] = make_float2(acc[mt][nt][2], acc[mt][nt][3]);
        }
    }
}

// ---------------------------------------------------------------------------
// K2: fused adj-select + leaky-relu + softmax -> fp16 alpha (single plane)
// ---------------------------------------------------------------------------
__global__ __launch_bounds__(256) void k_sel_softmax(const int* __restrict__ adj)
{
    const int w    = threadIdx.x >> 5;
    const int lane = threadIdx.x & 31;
    const size_t row = (size_t)blockIdx.x * 8 + w;
    const int b = (int)(row >> 9);
    const int i = (int)(row & 511);

    const size_t pstride = (size_t)NN * NN;
    const float* e0 = g_e + (((size_t)b * 4 + 0) * NN + i) * NN;
    const float* e1 = e0 + pstride;
    const float* e2 = e1 + pstride;
    const float* e3 = e2 + pstride;
    const int* ar = adj + row * NN;

    float v[16];
#pragma unroll
    for (int q = 0; q < 4; q++) {
        const int idx = q * 32 + lane;
        const float4 x0 = ((const float4*)e0)[idx];
        const float4 x1 = ((const float4*)e1)[idx];
        const float4 x2 = ((const float4*)e2)[idx];
        const float4 x3 = ((const float4*)e3)[idx];
        const int4   c  = ((const int4*)ar)[idx];
        const int   cc[4] = {c.x, c.y, c.z, c.w};
        const float f0[4] = {x0.x, x0.y, x0.z, x0.w};
        const float f1[4] = {x1.x, x1.y, x1.z, x1.w};
        const float f2[4] = {x2.x, x2.y, x2.z, x2.w};
        const float f3[4] = {x3.x, x3.y, x3.z, x3.w};
#pragma unroll
        for (int j = 0; j < 4; j++) {
            const int c1 = cc[j];
            float e;
            if      (c1 == 1) e = f0[j];
            else if (c1 == 2) e = f1[j];
            else if (c1 == 3) e = f2[j];
            else if (c1 == 4) e = f3[j];
            else { v[q * 4 + j] = NEG_INF; continue; }
            v[q * 4 + j] = (e > 0.f) ? e : 0.2f * e;
        }
    }

    float m = v[0];
#pragma unroll
    for (int q = 1; q < 16; q++) m = fmaxf(m, v[q]);
#pragma unroll
    for (int o = 16; o > 0; o >>= 1) m = fmaxf(m, __shfl_xor_sync(0xffffffffu, m, o));

    float sum = 0.f;
#pragma unroll
    for (int q = 0; q < 16; q++) { v[q] = __expf(v[q] - m); sum += v[q]; }
#pragma unroll
    for (int o = 16; o > 0; o >>= 1) sum += __shfl_xor_sync(0xffffffffu, sum, o);

    const float inv = 1.f / sum;
    __half* ap = g_a + row * NN;
#pragma unroll
    for (int q = 0; q < 4; q++) {
        const int idx = q * 32 + lane;
        __half hb[4];
#pragma unroll
        for (int j = 0; j < 4; j++)
            hb[j] = __float2half_rn(v[q * 4 + j] * inv);
        ((__half2*)(ap + idx * 4))[0] = __half2(hb[0], hb[1]);
        ((__half2*)(ap + idx * 4))[1] = __half2(hb[2], hb[3]);
    }
}

// ---------------------------------------------------------------------------
// K3: out = alpha @ h. Alpha unsplit fp16 (2 passes: a*bhi + a*blo).
// 2-stage cp.async, one barrier per chunk. Pass-grouped MMA order (dist 4).
// ---------------------------------------------------------------------------
#define VBS 136                        // 128 fp16 + 8 pad
#define V_APLANE (128 * SAS)
#define V_BPLANE (32 * VBS)
#define V_STAGE  (V_APLANE + 2 * V_BPLANE)
#define V_SMEM_BYTES (2 * V_STAGE * 2)

__global__ void __launch_bounds__(256, 2) k_av_tc(float* __restrict__ out)
{
    extern __shared__ __half sm[];

    const int t    = threadIdx.x;
    const int w    = t >> 5;
    const int lane = t & 31;
    const int wi   = w & 3;
    const int wj   = w >> 2;
    const int b    = blockIdx.z;
    const int i0   = blockIdx.y * 128;
    const int d0   = blockIdx.x * 128;

    const uint32_t smu = smem_to_u32(sm);

    const size_t aoff = ((size_t)b * NN + i0) * NN;
    const size_t boff = (size_t)b * NN * DD;
    const __half* gA0 = g_a + aoff;
    const __half* gB0 = g_bhi + boff;
    const __half* gB1 = g_blo + boff;

    float acc[2][8][4];
#pragma unroll
    for (int m = 0; m < 2; m++)
#pragma unroll
        for (int n = 0; n < 8; n++)
#pragma unroll
            for (int q = 0; q < 4; q++) acc[m][n][q] = 0.f;

    const uint32_t a_row  = wi * 32 + (lane & 15);
    const uint32_t a_colb = (lane >> 4) * 8;
    const uint32_t bt_row = lane & 15;
    const uint32_t bt_col = wj * 64 + (lane >> 4) * 8;

    auto load_stage = [&](int st, int j0c) {
        const uint32_t s0 = smu + (uint32_t)(st * V_STAGE) * 2;
#pragma unroll
        for (int q = t; q < 512; q += 256) {
            const int r = q >> 2;
            const int c = (q & 3) * 8;
            const uint32_t so = (uint32_t)(r * SAS + c) * 2;
            cp16(s0 + so, gA0 + (size_t)r * NN + j0c + c);
        }
#pragma unroll
        for (int q = t; q < 512; q += 256) {
            const int r = q >> 4;
            const int c = (q & 15) * 8;
            const uint32_t so = (uint32_t)(r * VBS + c) * 2;
            const size_t go = (size_t)(j0c + r) * DD + d0 + c;
            cp16(s0 + V_APLANE * 2 + so, gB0 + go);
            cp16(s0 + V_APLANE * 2 + V_BPLANE * 2 + so, gB1 + go);
        }
    };

    load_stage(0, 0);
    CP_COMMIT();

    const int NCH = NN / 32;   // 16 chunks
    for (int c = 0; c < NCH; c++) {
        CP_WAIT0();
        __syncthreads();
        if (c + 1 < NCH) {
            load_stage((c + 1) & 1, (c + 1) * 32);
            CP_COMMIT();
        }

        const uint32_t s0   = smu + (uint32_t)((c & 1) * V_STAGE) * 2;
        const uint32_t sA   = s0;
        const uint32_t sBhi = s0 + V_APLANE * 2;
        const uint32_t sBlo = sBhi + V_BPLANE * 2;

#pragma unroll
        for (int ks = 0; ks < 2; ks++) {
            uint32_t afr[2][4];
#pragma unroll
            for (int mt = 0; mt < 2; mt++) {
                const uint32_t off = ((a_row + mt * 16) * SAS + ks * 16 + a_colb) * 2;
                ldm_x4(afr[mt], sA + off);
            }
#pragma unroll
            for (int ntp = 0; ntp < 4; ntp++) {
                uint32_t bh[4], bl[4];
                const uint32_t off = ((ks * 16 + bt_row) * VBS + bt_col + ntp * 16) * 2;
                ldm_x4_trans(bh, sBhi + off);
                ldm_x4_trans(bl, sBlo + off);
                // pass 1: a * bhi  (4 independent, reuse distance 4)
                mma16816(acc[0][ntp*2],   afr[0], bh);
                mma16816(acc[0][ntp*2+1], afr[0], bh + 2);
                mma16816(acc[1][ntp*2],   afr[1], bh);
                mma16816(acc[1][ntp*2+1], afr[1], bh + 2);
                // pass 2: a * blo
                mma16816(acc[0][ntp*2],   afr[0], bl);
                mma16816(acc[0][ntp*2+1], afr[0], bl + 2);
                mma16816(acc[1][ntp*2],   afr[1], bl);
                mma16816(acc[1][ntp*2+1], afr[1], bl + 2);
            }
        }
    }

    const int g  = lane >> 2;
    const int tt = lane & 3;
    float* obase = out + ((size_t)b * NN + i0) * DD + d0;
#pragma unroll
    for (int mt = 0; mt < 2; mt++) {
        const int r0 = wi * 32 + mt * 16 + g;
#pragma unroll
        for (int nt = 0; nt < 8; nt++) {
            const int c0 = wj * 64 + nt * 8 + tt * 2;
            *(float2*)&obase[(size_t)r0 * DD + c0]       = make_float2(acc[mt][nt][0], acc[mt][nt][1]);
            *(float2*)&obase[(size_t)(r0 + 8) * DD + c0] = make_float2(acc[mt][nt][2], acc[mt][nt][3]);
        }
    }
}

// ---------------------------------------------------------------------------
extern "C" void kernel_launch(void* const* d_in, const int* in_sizes, int n_in,
                              void* d_out, int out_size)
{
    const float* hidden = (const float*)d_in[0];
    const int*   adj    = (const int*)d_in[1];
    const float* a0     = (const float*)d_in[2];
    const float* a1     = (const float*)d_in[3];
    const float* a2     = (const float*)d_in[4];
    const float* a3     = (const float*)d_in[5];
    float* out = (float*)d_out;

    cudaFuncSetAttribute(k_scores_tc,
        cudaFuncAttributeMaxDynamicSharedMemorySize, S_SMEM_BYTES);
    cudaFuncSetAttribute(k_av_tc,
        cudaFuncAttributeMaxDynamicSharedMemorySize, V_SMEM_BYTES);

    k_split<<<(BB * NN * DD / 4) / 256, 256>>>(hidden, a0, a1, a2, a3);

    dim3 g1(NN / 128, 16, BB);
    k_scores_tc<<<g1, 256, S_SMEM_BYTES>>>();

    k_sel_softmax<<<(BB * NN) / 8, 256>>>(adj);

    dim3 g3(DD / 128, NN / 128, BB);
    k_av_tc<<<g3, 256, V_SMEM_BYTES>>>(out);
}

// round 11
// speedup vs baseline: 1.1310x; 1.0624x over previous
#include <cuda_runtime.h>
#include <cuda_fp16.h>
#include <cstdint>

#define BB 32
#define NN 512
#define DD 256
#define NEG_INF -9e15f

// ---------------------------------------------------------------------------
// Device scratch (no allocation allowed)
// ---------------------------------------------------------------------------
__device__ float g_s[(size_t)BB * NN * NN];            // selected scores (NEG_INF init)
__device__ __half g_a[(size_t)BB * NN * NN];           // alpha (fp16, unsplit)
__device__ __half g_whi[(size_t)BB * 4 * NN * DD];     // (h*a_k) hi
__device__ __half g_wlo[(size_t)BB * 4 * NN * DD];     // (h*a_k) lo
__device__ __half g_bhi[(size_t)BB * NN * DD];         // h hi
__device__ __half g_blo[(size_t)BB * NN * DD];         // h lo

// ---------------------------------------------------------------------------
// mma.sync / cp.async helpers (portable sm_80+ path; tcgen05 blocked by the
// harness's compute_103 PTX stage)
// ---------------------------------------------------------------------------
__device__ __forceinline__ uint32_t smem_to_u32(const void* p) {
    uint32_t a;
    asm("{ .reg .u64 t; cvta.to.shared.u64 t, %1; cvt.u32.u64 %0, t; }"
        : "=r"(a) : "l"(p));
    return a;
}
__device__ __forceinline__ void ldm_x4(uint32_t* r, uint32_t addr) {
    asm volatile("ldmatrix.sync.aligned.m8n8.x4.shared.b16 {%0,%1,%2,%3}, [%4];"
        : "=r"(r[0]), "=r"(r[1]), "=r"(r[2]), "=r"(r[3]) : "r"(addr));
}
__device__ __forceinline__ void ldm_x4_trans(uint32_t* r, uint32_t addr) {
    asm volatile("ldmatrix.sync.aligned.m8n8.x4.trans.shared.b16 {%0,%1,%2,%3}, [%4];"
        : "=r"(r[0]), "=r"(r[1]), "=r"(r[2]), "=r"(r[3]) : "r"(addr));
}
__device__ __forceinline__ void mma16816(float* c, const uint32_t* a, const uint32_t* b) {
    asm volatile(
        "mma.sync.aligned.m16n8k16.row.col.f32.f16.f16.f32 "
        "{%0,%1,%2,%3}, {%4,%5,%6,%7}, {%8,%9}, {%0,%1,%2,%3};"
        : "+f"(c[0]), "+f"(c[1]), "+f"(c[2]), "+f"(c[3])
        : "r"(a[0]), "r"(a[1]), "r"(a[2]), "r"(a[3]), "r"(b[0]), "r"(b[1]));
}
__device__ __forceinline__ void cp16(uint32_t dst, const void* src) {
    asm volatile("cp.async.cg.shared.global [%0], [%1], 16;" :: "r"(dst), "l"(src));
}
#define CP_COMMIT() asm volatile("cp.async.commit_group;" ::: "memory")
#define CP_WAIT0()  asm volatile("cp.async.wait_group 0;" ::: "memory")

// ---------------------------------------------------------------------------
// K0: split h and w_k = h*a_k into fp16 hi/lo planes; init g_s to NEG_INF
// ---------------------------------------------------------------------------
__device__ __forceinline__ void f16pair_store(
    __half* hi, __half* lo, float4 v)
{
    float f[4] = {v.x, v.y, v.z, v.w};
    __half hb[4], lb[4];
#pragma unroll
    for (int j = 0; j < 4; j++) {
        hb[j] = __float2half_rn(f[j]);
        lb[j] = __float2half_rn(f[j] - __half2float(hb[j]));
    }
    ((__half2*)hi)[0] = __half2(hb[0], hb[1]);
    ((__half2*)hi)[1] = __half2(hb[2], hb[3]);
    ((__half2*)lo)[0] = __half2(lb[0], lb[1]);
    ((__half2*)lo)[1] = __half2(lb[2], lb[3]);
}

__global__ __launch_bounds__(256) void k_split(
    const float* __restrict__ h,
    const float* __restrict__ a0, const float* __restrict__ a1,
    const float* __restrict__ a2, const float* __restrict__ a3)
{
    const int idx = blockIdx.x * 256 + threadIdx.x;   // [0, B*N*D/4)
    const int row = idx >> 6;
    const int c4  = idx & 63;
    const int d   = c4 * 4;
    const float4 hv = ((const float4*)h)[idx];

    // init selected-score plane to NEG_INF: 8 floats per thread covers B*N*N
    {
        const float4 n4 = make_float4(NEG_INF, NEG_INF, NEG_INF, NEG_INF);
        ((float4*)g_s)[(size_t)idx * 2]     = n4;
        ((float4*)g_s)[(size_t)idx * 2 + 1] = n4;
    }

    {
        size_t off = (size_t)row * DD + d;
        f16pair_store(g_bhi + off, g_blo + off, hv);
    }
    const int b = row >> 9, i = row & 511;
    const float* aks[4] = {a0, a1, a2, a3};
#pragma unroll
    for (int k = 0; k < 4; k++) {
        const float4 av = ((const float4*)aks[k])[c4];
        float4 wv = make_float4(hv.x * av.x, hv.y * av.y, hv.z * av.z, hv.w * av.w);
        size_t off = (((size_t)b * 4 + k) * NN + i) * DD + d;
        f16pair_store(g_whi + off, g_wlo + off, wv);
    }
}

// ---------------------------------------------------------------------------
// K1: tensor scores (fp16 hi/lo 3-pass) with fused adj-select + leaky-relu.
// CTA = (b, head, 128i x 128j). Heads write DISJOINT elements (adj==k+1
// partitions) into the shared NEG_INF-initialized plane g_s — no races.
// ---------------------------------------------------------------------------
#define SAS 40                       // 32 fp16 + 8 pad
#define S_PLANE (128 * SAS)
#define S_STAGE (4 * S_PLANE)        // whi, wlo, bhi, blo
#define S_SMEM_BYTES (2 * S_STAGE * 2)

__global__ void __launch_bounds__(256, 2) k_scores_tc(const int* __restrict__ adj)
{
    extern __shared__ __half sm[];

    const int t    = threadIdx.x;
    const int w    = t >> 5;
    const int lane = t & 31;
    const int wi   = w & 3;
    const int wj   = w >> 2;
    const int b    = blockIdx.z;
    const int k    = blockIdx.y >> 2;
    const int i0   = (blockIdx.y & 3) * 128;
    const int j0   = blockIdx.x * 128;

    const uint32_t smu = smem_to_u32(sm);

    const size_t aoff = (((size_t)b * 4 + k) * NN + i0) * DD;
    const size_t boff = ((size_t)b * NN + j0) * DD;
    const __half* gA0 = g_whi + aoff;
    const __half* gA1 = g_wlo + aoff;
    const __half* gB0 = g_bhi + boff;
    const __half* gB1 = g_blo + boff;

    float acc[2][8][4];
#pragma unroll
    for (int m = 0; m < 2; m++)
#pragma unroll
        for (int n = 0; n < 8; n++)
#pragma unroll
            for (int q = 0; q < 4; q++) acc[m][n][q] = 0.f;

    const uint32_t a_row  = wi * 32 + (lane & 15);
    const uint32_t a_colb = (lane >> 4) * 8;
    const uint32_t b_row  = wj * 64 + (lane & 7) + (lane >> 4) * 8;
    const uint32_t b_colb = ((lane >> 3) & 1) * 8;

    auto load_stage = [&](int st, int d0) {
        const uint32_t s0 = smu + (uint32_t)(st * S_STAGE) * 2;
#pragma unroll
        for (int q = t; q < 512; q += 256) {
            const int r = q >> 2;
            const int c = (q & 3) * 8;
            const uint32_t so = (uint32_t)(r * SAS + c) * 2;
            const size_t go = (size_t)r * DD + d0 + c;
            cp16(s0 + 0 * S_PLANE * 2 + so, gA0 + go);
            cp16(s0 + 1 * S_PLANE * 2 + so, gA1 + go);
            cp16(s0 + 2 * S_PLANE * 2 + so, gB0 + go);
            cp16(s0 + 3 * S_PLANE * 2 + so, gB1 + go);
        }
    };

    load_stage(0, 0);
    CP_COMMIT();

    const int NCH = DD / 32;   // 8 chunks
    for (int c = 0; c < NCH; c++) {
        CP_WAIT0();
        __syncthreads();
        if (c + 1 < NCH) {
            load_stage((c + 1) & 1, (c + 1) * 32);
            CP_COMMIT();
        }

        const uint32_t s0   = smu + (uint32_t)((c & 1) * S_STAGE) * 2;
        const uint32_t sWhi = s0;
        const uint32_t sWlo = s0 + 1 * S_PLANE * 2;
        const uint32_t sBhi = s0 + 2 * S_PLANE * 2;
        const uint32_t sBlo = s0 + 3 * S_PLANE * 2;

#pragma unroll
        for (int ks = 0; ks < 2; ks++) {
            uint32_t ahi[2][4], alo[2][4];
#pragma unroll
            for (int mt = 0; mt < 2; mt++) {
                const uint32_t off = ((a_row + mt * 16) * SAS + ks * 16 + a_colb) * 2;
                ldm_x4(ahi[mt], sWhi + off);
                ldm_x4(alo[mt], sWlo + off);
            }
#pragma unroll
            for (int ntp = 0; ntp < 4; ntp++) {
                uint32_t bh[4], bl[4];
                const uint32_t off = ((b_row + ntp * 16) * SAS + ks * 16 + b_colb) * 2;
                ldm_x4(bh, sBhi + off);
                ldm_x4(bl, sBlo + off);
                // pass 1: ahi * bh
                mma16816(acc[0][ntp*2],   ahi[0], bh);
                mma16816(acc[0][ntp*2+1], ahi[0], bh + 2);
                mma16816(acc[1][ntp*2],   ahi[1], bh);
                mma16816(acc[1][ntp*2+1], ahi[1], bh + 2);
                // pass 2: ahi * bl
                mma16816(acc[0][ntp*2],   ahi[0], bl);
                mma16816(acc[0][ntp*2+1], ahi[0], bl + 2);
                mma16816(acc[1][ntp*2],   ahi[1], bl);
                mma16816(acc[1][ntp*2+1], ahi[1], bl + 2);
                // pass 3: alo * bh
                mma16816(acc[0][ntp*2],   alo[0], bh);
                mma16816(acc[0][ntp*2+1], alo[0], bh + 2);
                mma16816(acc[1][ntp*2],   alo[1], bh);
                mma16816(acc[1][ntp*2+1], alo[1], bh + 2);
            }
        }
    }

    // epilogue: predicated disjoint writes where adj == k+1 (leaky applied)
    const int g  = lane >> 2;
    const int tt = lane & 3;
    const int want = k + 1;
    float* plane    = g_s + ((size_t)b * NN + i0) * NN + j0;
    const int* adjp = adj + ((size_t)b * NN + i0) * NN + j0;
#pragma unroll
    for (int mt = 0; mt < 2; mt++) {
        const int r0 = wi * 32 + mt * 16 + g;
#pragma unroll
        for (int nt = 0; nt < 8; nt++) {
            const int c0 = wj * 64 + nt * 8 + tt * 2;
#pragma unroll
            for (int hrow = 0; hrow < 2; hrow++) {
                const size_t off = (size_t)(r0 + hrow * 8) * NN + c0;
                const int2 ad = *(const int2*)&adjp[off];
                const float v0 = acc[mt][nt][hrow * 2 + 0];
                const float v1 = acc[mt][nt][hrow * 2 + 1];
                if (ad.x == want) plane[off]     = (v0 > 0.f) ? v0 : 0.2f * v0;
                if (ad.y == want) plane[off + 1] = (v1 > 0.f) ? v1 : 0.2f * v1;
            }
        }
    }
}

// ---------------------------------------------------------------------------
// K2: row softmax on selected plane -> fp16 alpha (single plane read)
// ---------------------------------------------------------------------------
__global__ __launch_bounds__(256) void k_softmax()
{
    const int w    = threadIdx.x >> 5;
    const int lane = threadIdx.x & 31;
    const size_t row = (size_t)blockIdx.x * 8 + w;
    const float* p = g_s + row * NN;

    float v[16];
#pragma unroll
    for (int q = 0; q < 4; q++) {
        const float4 x = ((const float4*)p)[q * 32 + lane];
        v[q*4+0] = x.x; v[q*4+1] = x.y; v[q*4+2] = x.z; v[q*4+3] = x.w;
    }

    float m = v[0];
#pragma unroll
    for (int q = 1; q < 16; q++) m = fmaxf(m, v[q]);
#pragma unroll
    for (int o = 16; o > 0; o >>= 1) m = fmaxf(m, __shfl_xor_sync(0xffffffffu, m, o));

    float sum = 0.f;
#pragma unroll
    for (int q = 0; q < 16; q++) { v[q] = __expf(v[q] - m); sum += v[q]; }
#pragma unroll
    for (int o = 16; o > 0; o >>= 1) sum += __shfl_xor_sync(0xffffffffu, sum, o);

    const float inv = 1.f / sum;
    __half* ap = g_a + row * NN;
#pragma unroll
    for (int q = 0; q < 4; q++) {
        const int idx = q * 32 + lane;
        __half hb[4];
#pragma unroll
        for (int j = 0; j < 4; j++)
            hb[j] = __float2half_rn(v[q * 4 + j] * inv);
        ((__half2*)(ap + idx * 4))[0] = __half2(hb[0], hb[1]);
        ((__half2*)(ap + idx * 4))[1] = __half2(hb[2], hb[3]);
    }
}

// ---------------------------------------------------------------------------
// K3: out = alpha @ h. Alpha unsplit fp16 (2 passes: a*bhi + a*blo).
// 2-stage cp.async, one barrier per chunk. Pass-grouped MMA order.
// ---------------------------------------------------------------------------
#define VBS 136                        // 128 fp16 + 8 pad
#define V_APLANE (128 * SAS)
#define V_BPLANE (32 * VBS)
#define V_STAGE  (V_APLANE + 2 * V_BPLANE)
#define V_SMEM_BYTES (2 * V_STAGE * 2)

__global__ void __launch_bounds__(256, 2) k_av_tc(float* __restrict__ out)
{
    extern __shared__ __half sm[];

    const int t    = threadIdx.x;
    const int w    = t >> 5;
    const int lane = t & 31;
    const int wi   = w & 3;
    const int wj   = w >> 2;
    const int b    = blockIdx.z;
    const int i0   = blockIdx.y * 128;
    const int d0   = blockIdx.x * 128;

    const uint32_t smu = smem_to_u32(sm);

    const size_t aoff = ((size_t)b * NN + i0) * NN;
    const size_t boff = (size_t)b * NN * DD;
    const __half* gA0 = g_a + aoff;
    const __half* gB0 = g_bhi + boff;
    const __half* gB1 = g_blo + boff;

    float acc[2][8][4];
#pragma unroll
    for (int m = 0; m < 2; m++)
#pragma unroll
        for (int n = 0; n < 8; n++)
#pragma unroll
            for (int q = 0; q < 4; q++) acc[m][n][q] = 0.f;

    const uint32_t a_row  = wi * 32 + (lane & 15);
    const uint32_t a_colb = (lane >> 4) * 8;
    const uint32_t bt_row = lane & 15;
    const uint32_t bt_col = wj * 64 + (lane >> 4) * 8;

    auto load_stage = [&](int st, int j0c) {
        const uint32_t s0 = smu + (uint32_t)(st * V_STAGE) * 2;
#pragma unroll
        for (int q = t; q < 512; q += 256) {
            const int r = q >> 2;
            const int c = (q & 3) * 8;
            const uint32_t so = (uint32_t)(r * SAS + c) * 2;
            cp16(s0 + so, gA0 + (size_t)r * NN + j0c + c);
        }
#pragma unroll
        for (int q = t; q < 512; q += 256) {
            const int r = q >> 4;
            const int c = (q & 15) * 8;
            const uint32_t so = (uint32_t)(r * VBS + c) * 2;
            const size_t go = (size_t)(j0c + r) * DD + d0 + c;
            cp16(s0 + V_APLANE * 2 + so, gB0 + go);
            cp16(s0 + V_APLANE * 2 + V_BPLANE * 2 + so, gB1 + go);
        }
    };

    load_stage(0, 0);
    CP_COMMIT();

    const int NCH = NN / 32;   // 16 chunks
    for (int c = 0; c < NCH; c++) {
        CP_WAIT0();
        __syncthreads();
        if (c + 1 < NCH) {
            load_stage((c + 1) & 1, (c + 1) * 32);
            CP_COMMIT();
        }

        const uint32_t s0   = smu + (uint32_t)((c & 1) * V_STAGE) * 2;
        const uint32_t sA   = s0;
        const uint32_t sBhi = s0 + V_APLANE * 2;
        const uint32_t sBlo = sBhi + V_BPLANE * 2;

#pragma unroll
        for (int ks = 0; ks < 2; ks++) {
            uint32_t afr[2][4];
#pragma unroll
            for (int mt = 0; mt < 2; mt++) {
                const uint32_t off = ((a_row + mt * 16) * SAS + ks * 16 + a_colb) * 2;
                ldm_x4(afr[mt], sA + off);
            }
#pragma unroll
            for (int ntp = 0; ntp < 4; ntp++) {
                uint32_t bh[4], bl[4];
                const uint32_t off = ((ks * 16 + bt_row) * VBS + bt_col + ntp * 16) * 2;
                ldm_x4_trans(bh, sBhi + off);
                ldm_x4_trans(bl, sBlo + off);
                // pass 1: a * bhi
                mma16816(acc[0][ntp*2],   afr[0], bh);
                mma16816(acc[0][ntp*2+1], afr[0], bh + 2);
                mma16816(acc[1][ntp*2],   afr[1], bh);
                mma16816(acc[1][ntp*2+1], afr[1], bh + 2);
                // pass 2: a * blo
                mma16816(acc[0][ntp*2],   afr[0], bl);
                mma16816(acc[0][ntp*2+1], afr[0], bl + 2);
                mma16816(acc[1][ntp*2],   afr[1], bl);
                mma16816(acc[1][ntp*2+1], afr[1], bl + 2);
            }
        }
    }

    const int g  = lane >> 2;
    const int tt = lane & 3;
    float* obase = out + ((size_t)b * NN + i0) * DD + d0;
#pragma unroll
    for (int mt = 0; mt < 2; mt++) {
        const int r0 = wi * 32 + mt * 16 + g;
#pragma unroll
        for (int nt = 0; nt < 8; nt++) {
            const int c0 = wj * 64 + nt * 8 + tt * 2;
            *(float2*)&obase[(size_t)r0 * DD + c0]       = make_float2(acc[mt][nt][0], acc[mt][nt][1]);
            *(float2*)&obase[(size_t)(r0 + 8) * DD + c0] = make_float2(acc[mt][nt][2], acc[mt][nt][3]);
        }
    }
}

// ---------------------------------------------------------------------------
extern "C" void kernel_launch(void* const* d_in, const int* in_sizes, int n_in,
                              void* d_out, int out_size)
{
    const float* hidden = (const float*)d_in[0];
    const int*   adj    = (const int*)d_in[1];
    const float* a0     = (const float*)d_in[2];
    const float* a1     = (const float*)d_in[3];
    const float* a2     = (const float*)d_in[4];
    const float* a3     = (const float*)d_in[5];
    float* out = (float*)d_out;

    cudaFuncSetAttribute(k_scores_tc,
        cudaFuncAttributeMaxDynamicSharedMemorySize, S_SMEM_BYTES);
    cudaFuncSetAttribute(k_av_tc,
        cudaFuncAttributeMaxDynamicSharedMemorySize, V_SMEM_BYTES);

    k_split<<<(BB * NN * DD / 4) / 256, 256>>>(hidden, a0, a1, a2, a3);

    dim3 g1(NN / 128, 16, BB);
    k_scores_tc<<<g1, 256, S_SMEM_BYTES>>>(adj);

    k_softmax<<<(BB * NN) / 8, 256>>>();

    dim3 g3(DD / 128, NN / 128, BB);
    k_av_tc<<<g3, 256, V_SMEM_BYTES>>>(out);
}